// round 7
// baseline (speedup 1.0000x reference)
#include <cuda_runtime.h>
#include <cuda_bf16.h>
#include <cstdint>

#define N_NODES 100000
#define N_EDGES 3200000
#define IN_CH   128
#define HID     32
#define OUT_CH  64
#define N_SG    31
#define N_TOT   (N_EDGES + N_NODES)   // edges + self loops

// ---------------- device scratch (static globals; no allocation) ----------------
__device__ int   g_is64;                       // 1 if edge_index is int64, 0 if int32
__device__ int   g_deg[N_NODES];
__device__ float g_dinv[N_NODES];
__device__ int   g_offs[N_NODES + 1];
__device__ int   g_cursor[N_NODES];
__device__ int2  g_csr[N_TOT];                 // {src, bitcast(norm)} grouped by dst
__device__ float g_h[2][(size_t)N_NODES * HID]; // ping-pong hidden state

// Safe edge accessor: idx in [0, 2*N_EDGES)
__device__ __forceinline__ int edge_at(const void* ei, size_t idx) {
    int v = g_is64 ? (int)((const long long*)ei)[idx]
                   : ((const int*)ei)[idx];
    // clamp defensively (avoids IMA if dtype/layout model is wrong)
    return min(max(v, 0), N_NODES - 1);
}

// ---------------- dtype detection ----------------
// Read buffer as int32 words. Only touches words [0, 2*N_EDGES) which is safe
// for BOTH dtypes (int32: 6.4M words total; int64: 12.8M words total).
// If int64 with values < 2^31, every odd word in this range is 0.
__global__ void k_detect(const int* __restrict__ w) {
    __shared__ int any_nonzero;
    if (threadIdx.x == 0) any_nonzero = 0;
    __syncthreads();
    // 1024 threads sample odd words spread over [0, 6.4M)
    size_t pos = (size_t)threadIdx.x * 6247 * 2 + 1;   // < 6.4M for tid<1024
    if (w[pos] != 0) any_nonzero = 1;
    __syncthreads();
    if (threadIdx.x == 0) g_is64 = any_nonzero ? 0 : 1;
}

// ---------------- preprocessing ----------------
__global__ void k_init_deg() {
    int i = blockIdx.x * blockDim.x + threadIdx.x;
    if (i < N_NODES) g_deg[i] = 1;  // self loop
}

__global__ void k_deg_accum(const void* __restrict__ ei) {
    int i = blockIdx.x * blockDim.x + threadIdx.x;
    if (i < N_EDGES) {
        int c = edge_at(ei, (size_t)N_EDGES + i);   // col = edge_index[1]
        atomicAdd(&g_deg[c], 1);
    }
}

__global__ void k_dinv() {
    int i = blockIdx.x * blockDim.x + threadIdx.x;
    if (i < N_NODES) g_dinv[i] = rsqrtf((float)g_deg[i]);
}

// single-block exclusive scan of g_deg -> g_offs (N=100k, 1024 threads)
__global__ void k_scan() {
    __shared__ int part[1024];
    const int tid = threadIdx.x;
    const int chunk = (N_NODES + 1023) / 1024;
    int beg = tid * chunk;
    int end = min(beg + chunk, N_NODES);
    int s = 0;
    for (int i = beg; i < end; i++) s += g_deg[i];
    part[tid] = s;
    __syncthreads();
    for (int off = 1; off < 1024; off <<= 1) {
        int v = (tid >= off) ? part[tid - off] : 0;
        __syncthreads();
        part[tid] += v;
        __syncthreads();
    }
    int run = (tid == 0) ? 0 : part[tid - 1];
    for (int i = beg; i < end; i++) { g_offs[i] = run; run += g_deg[i]; }
    if (tid == 1023) g_offs[N_NODES] = run;  // == N_TOT
}

__global__ void k_cursor() {
    int i = blockIdx.x * blockDim.x + threadIdx.x;
    if (i < N_NODES) g_cursor[i] = g_offs[i];
}

__global__ void k_fill(const void* __restrict__ ei) {
    int i = blockIdx.x * blockDim.x + threadIdx.x;
    if (i < N_EDGES) {
        int r = edge_at(ei, (size_t)i);               // row = edge_index[0] (src)
        int c = edge_at(ei, (size_t)N_EDGES + i);     // col = edge_index[1] (dst)
        int pos = atomicAdd(&g_cursor[c], 1);
        pos = min(max(pos, 0), N_TOT - 1);
        g_csr[pos] = make_int2(r, __float_as_int(g_dinv[r] * g_dinv[c]));
    } else if (i < N_TOT) {
        int n = i - N_EDGES;
        int pos = atomicAdd(&g_cursor[n], 1);
        pos = min(max(pos, 0), N_TOT - 1);
        float d = g_dinv[n];
        g_csr[pos] = make_int2(n, __float_as_int(d * d));
    }
}

// ---------------- conv0: h0 = x @ W0 + b0   (warp per node) ----------------
__global__ void k_conv0(const float* __restrict__ x, const float* __restrict__ W0,
                        const float* __restrict__ b0) {
    __shared__ float Wsm[IN_CH * HID];   // 16 KB
    __shared__ float bsm[HID];
    for (int i = threadIdx.x; i < IN_CH * HID; i += blockDim.x) Wsm[i] = W0[i];
    if (threadIdx.x < HID) bsm[threadIdx.x] = b0[threadIdx.x];
    __syncthreads();
    int warp = blockIdx.x * (blockDim.x >> 5) + (threadIdx.x >> 5);
    int lane = threadIdx.x & 31;
    if (warp >= N_NODES) return;
    float xr[4];
#pragma unroll
    for (int q = 0; q < 4; q++) xr[q] = x[(size_t)warp * IN_CH + q * 32 + lane];
    float y = bsm[lane];
#pragma unroll
    for (int q = 0; q < 4; q++)
#pragma unroll
        for (int c = 0; c < 32; c++) {
            float xv = __shfl_sync(0xffffffffu, xr[q], c);
            y = fmaf(xv, Wsm[(q * 32 + c) * HID + lane], y);
        }
    g_h[0][(size_t)warp * HID + lane] = y;   // no relu on conv0
}

// ---------------- SG layer: agg = sum_e w*h[src]; h = relu(agg@W + b) ----------------
__global__ void __launch_bounds__(256) k_sg_layer(int parity, const float* __restrict__ W,
                                                  const float* __restrict__ b) {
    __shared__ float Wsm[HID * HID];
    __shared__ float bsm[HID];
    for (int i = threadIdx.x; i < HID * HID; i += blockDim.x) Wsm[i] = W[i];
    if (threadIdx.x < HID) bsm[threadIdx.x] = b[threadIdx.x];
    __syncthreads();
    int node = blockIdx.x * (blockDim.x >> 5) + (threadIdx.x >> 5);
    int lane = threadIdx.x & 31;
    if (node >= N_NODES) return;

    const float* __restrict__ hin = g_h[parity];
    float* __restrict__ hout      = g_h[parity ^ 1];

    int e   = g_offs[node];
    int end = g_offs[node + 1];
    float acc = 0.f;
    for (; e + 4 <= end; e += 4) {
        int2 p0 = g_csr[e], p1 = g_csr[e + 1], p2 = g_csr[e + 2], p3 = g_csr[e + 3];
        float v0 = hin[(size_t)p0.x * HID + lane];
        float v1 = hin[(size_t)p1.x * HID + lane];
        float v2 = hin[(size_t)p2.x * HID + lane];
        float v3 = hin[(size_t)p3.x * HID + lane];
        acc = fmaf(__int_as_float(p0.y), v0, acc);
        acc = fmaf(__int_as_float(p1.y), v1, acc);
        acc = fmaf(__int_as_float(p2.y), v2, acc);
        acc = fmaf(__int_as_float(p3.y), v3, acc);
    }
    for (; e < end; e++) {
        int2 p = g_csr[e];
        acc = fmaf(__int_as_float(p.y), hin[(size_t)p.x * HID + lane], acc);
    }
    float y = bsm[lane];
#pragma unroll
    for (int c = 0; c < 32; c++)
        y = fmaf(__shfl_sync(0xffffffffu, acc, c), Wsm[c * HID + lane], y);
    hout[(size_t)node * HID + lane] = fmaxf(y, 0.f);
}

// ---------------- conv32: out = h @ W32 + b32  (warp per node, 2 outputs/lane) ----------------
__global__ void k_conv_out(int parity, const float* __restrict__ W32,
                           const float* __restrict__ b32, float* __restrict__ out) {
    __shared__ float Wsm[HID * OUT_CH];  // 8 KB
    __shared__ float bsm[OUT_CH];
    for (int i = threadIdx.x; i < HID * OUT_CH; i += blockDim.x) Wsm[i] = W32[i];
    if (threadIdx.x < OUT_CH) bsm[threadIdx.x] = b32[threadIdx.x];
    __syncthreads();
    int warp = blockIdx.x * (blockDim.x >> 5) + (threadIdx.x >> 5);
    int lane = threadIdx.x & 31;
    if (warp >= N_NODES) return;
    const float* __restrict__ hin = g_h[parity];
    float hv = hin[(size_t)warp * HID + lane];
    float y0 = bsm[lane], y1 = bsm[lane + 32];
#pragma unroll
    for (int c = 0; c < 32; c++) {
        float a = __shfl_sync(0xffffffffu, hv, c);
        y0 = fmaf(a, Wsm[c * OUT_CH + lane], y0);
        y1 = fmaf(a, Wsm[c * OUT_CH + lane + 32], y1);
    }
    out[(size_t)warp * OUT_CH + lane]      = y0;
    out[(size_t)warp * OUT_CH + lane + 32] = y1;
}

// ---------------- launch ----------------
extern "C" void kernel_launch(void* const* d_in, const int* in_sizes, int n_in,
                              void* d_out, int out_size) {
    // Bind inputs by UNIQUE element count (robust to metadata ordering):
    const float* x = nullptr; const float* W0 = nullptr; const float* b0 = nullptr;
    const float* Ws = nullptr; const float* bs = nullptr;
    const float* W32 = nullptr; const float* b32 = nullptr;
    const void* ei = nullptr;
    for (int i = 0; i < n_in; i++) {
        switch (in_sizes[i]) {
            case 12800000: x   = (const float*)d_in[i]; break;
            case 4096:     W0  = (const float*)d_in[i]; break;
            case 32:       b0  = (const float*)d_in[i]; break;
            case 31744:    Ws  = (const float*)d_in[i]; break;
            case 992:      bs  = (const float*)d_in[i]; break;
            case 2048:     W32 = (const float*)d_in[i]; break;
            case 64:       b32 = (const float*)d_in[i]; break;
            case 6400000:  ei  = d_in[i]; break;
            default: break;
        }
    }
    if (!x || !W0 || !b0 || !Ws || !bs || !W32 || !b32 || !ei) return;

    float* out = (float*)d_out;
    const int T = 256;

    // dtype probe + preprocessing: degrees, norms, CSR
    k_detect<<<1, 1024>>>((const int*)ei);
    k_init_deg<<<(N_NODES + T - 1) / T, T>>>();
    k_deg_accum<<<(N_EDGES + T - 1) / T, T>>>(ei);
    k_dinv<<<(N_NODES + T - 1) / T, T>>>();
    k_scan<<<1, 1024>>>();
    k_cursor<<<(N_NODES + T - 1) / T, T>>>();
    k_fill<<<(N_TOT + T - 1) / T, T>>>(ei);

    // warp-per-node grids: 8 warps / 256-thread block
    const int NODE_BLOCKS = (N_NODES + 7) / 8;  // 12500

    k_conv0<<<NODE_BLOCKS, T>>>(x, W0, b0);

    int parity = 0;
    for (int l = 0; l < N_SG; l++) {
        k_sg_layer<<<NODE_BLOCKS, T>>>(parity, Ws + (size_t)l * HID * HID, bs + (size_t)l * HID);
        parity ^= 1;
    }

    k_conv_out<<<NODE_BLOCKS, T>>>(parity, W32, b32, out);
}

// round 8
// speedup vs baseline: 1.2059x; 1.2059x over previous
#include <cuda_runtime.h>
#include <cuda_bf16.h>
#include <cstdint>

#define N_NODES 100000
#define N_EDGES 3200000
#define IN_CH   128
#define HID     32
#define OUT_CH  64
#define N_SG    31
#define N_RAW   (N_EDGES + N_NODES)          // edges + self loops (unpadded)
#define N_PAD_MAX (N_EDGES + 4 * N_NODES)    // padded CSR capacity (3.6M, mult of 4)

// ---------------- device scratch (static globals; no allocation) ----------------
__device__ int    g_is64;
__device__ int    g_deg[N_NODES];
__device__ float  g_dinv[N_NODES];
__device__ int    g_offs[N_NODES + 1];
__device__ int    g_cursor[N_NODES];
__device__ int4   g_csr4[N_PAD_MAX / 4];             // src indices, padded w/ sentinel N_NODES
__device__ float4 g_h[2][(size_t)(N_NODES + 1) * 8]; // ping-pong scaled state h' (row N_NODES = zeros)

// Safe edge accessor: idx in [0, 2*N_EDGES)
__device__ __forceinline__ int edge_at(const void* ei, size_t idx) {
    int v = g_is64 ? (int)((const long long*)ei)[idx]
                   : ((const int*)ei)[idx];
    return min(max(v, 0), N_NODES - 1);
}

// ---------------- launch 1: dtype detect + deg init ----------------
__global__ void k_detect_init(const int* __restrict__ w) {
    int i = blockIdx.x * blockDim.x + threadIdx.x;
    if (i < N_NODES) g_deg[i] = 1;  // self loop
    if (blockIdx.x == 0) {
        __shared__ int any_nonzero;
        if (threadIdx.x == 0) any_nonzero = 0;
        __syncthreads();
        // sample odd int32 words over [0, 6.4M): all-zero <=> int64 payload
        size_t pos = (size_t)threadIdx.x * 24994 + 1;   // tid<256 -> max 6.37M
        if (w[pos] != 0) any_nonzero = 1;
        __syncthreads();
        if (threadIdx.x == 0) g_is64 = any_nonzero ? 0 : 1;
    }
}

// ---------------- launch 2: degree accumulation ----------------
__global__ void k_deg_accum(const void* __restrict__ ei) {
    int i = blockIdx.x * blockDim.x + threadIdx.x;
    if (i < N_EDGES) {
        int c = edge_at(ei, (size_t)N_EDGES + i);   // col = edge_index[1] (dst)
        atomicAdd(&g_deg[c], 1);
    }
}

// ---------------- launch 3: dinv + padded exclusive scan (single block) ----------------
__global__ void k_scan_dinv() {
    __shared__ int part[1024];
    const int tid = threadIdx.x;
    const int chunk = (N_NODES + 1023) / 1024;
    int beg = tid * chunk;
    int end = min(beg + chunk, N_NODES);
    int s = 0;
    for (int i = beg; i < end; i++) {
        int d = g_deg[i];
        g_dinv[i] = rsqrtf((float)d);
        s += (d + 3) & ~3;                      // padded degree
    }
    part[tid] = s;
    __syncthreads();
    for (int off = 1; off < 1024; off <<= 1) {
        int v = (tid >= off) ? part[tid - off] : 0;
        __syncthreads();
        part[tid] += v;
        __syncthreads();
    }
    int run = (tid == 0) ? 0 : part[tid - 1];
    for (int i = beg; i < end; i++) { g_offs[i] = run; run += (g_deg[i] + 3) & ~3; }
    if (tid == 1023) g_offs[N_NODES] = run;
}

// ---------------- launch 4: cursor init + CSR sentinel fill + zero sentinel h rows ----------------
__global__ void k_prep() {
    int i = blockIdx.x * blockDim.x + threadIdx.x;
    if (i < N_NODES) g_cursor[i] = g_offs[i];
    if (i < N_PAD_MAX / 4) g_csr4[i] = make_int4(N_NODES, N_NODES, N_NODES, N_NODES);
    if (i < 64) {  // zero row N_NODES of both ping-pong buffers
        ((float*)g_h[i >> 5])[(size_t)N_NODES * 32 + (i & 31)] = 0.f;
    }
}

// ---------------- launch 5: CSR fill (+ self loops)  AND  conv0 (fused) ----------------
// blocks [0, FILL_B): fill; blocks [FILL_B, FILL_B+CONV_B): conv0 warp-per-node
#define FILL_B ((N_RAW + 255) / 256)         // 12891
#define CONV_B ((N_NODES + 7) / 8)           // 12500
__global__ void __launch_bounds__(256) k_fill_conv0(const void* __restrict__ ei,
                                                    const float* __restrict__ x,
                                                    const float* __restrict__ W0,
                                                    const float* __restrict__ b0) {
    __shared__ float Wsm[IN_CH * HID];   // 16 KB (used by conv0 blocks only)
    __shared__ float bsm[HID];
    if (blockIdx.x < FILL_B) {
        int i = blockIdx.x * blockDim.x + threadIdx.x;
        int* csr = (int*)g_csr4;
        if (i < N_EDGES) {
            int r = edge_at(ei, (size_t)i);               // src
            int c = edge_at(ei, (size_t)N_EDGES + i);     // dst
            int pos = atomicAdd(&g_cursor[c], 1);
            csr[min(max(pos, 0), N_PAD_MAX - 1)] = r;
        } else if (i < N_RAW) {
            int n = i - N_EDGES;
            int pos = atomicAdd(&g_cursor[n], 1);
            csr[min(max(pos, 0), N_PAD_MAX - 1)] = n;     // self loop
        }
        return;
    }
    // ---- conv0: h'0 = dinv * (x @ W0 + b0) ----
    for (int i = threadIdx.x; i < IN_CH * HID; i += blockDim.x) Wsm[i] = W0[i];
    if (threadIdx.x < HID) bsm[threadIdx.x] = b0[threadIdx.x];
    __syncthreads();
    int node = (blockIdx.x - FILL_B) * 8 + (threadIdx.x >> 5);
    int lane = threadIdx.x & 31;
    if (node >= N_NODES) return;
    float xr[4];
#pragma unroll
    for (int q = 0; q < 4; q++) xr[q] = x[(size_t)node * IN_CH + q * 32 + lane];
    float y = bsm[lane];
#pragma unroll
    for (int q = 0; q < 4; q++)
#pragma unroll
        for (int c = 0; c < 32; c++) {
            float xv = __shfl_sync(0xffffffffu, xr[q], c);
            y = fmaf(xv, Wsm[(q * 32 + c) * HID + lane], y);
        }
    ((float*)g_h[0])[(size_t)node * 32 + lane] = y * g_dinv[node];
}

// ---------------- launches 6..36: SG layer ----------------
// agg = dinv[dst] * sum_{src in N(dst)} h'[src];  h'_out = dinv[dst]*relu(agg@W + b)
__global__ void __launch_bounds__(256) k_sg_layer(int parity, const float* __restrict__ W,
                                                  const float* __restrict__ b) {
    __shared__ float Wsm[HID * HID];
    __shared__ float bsm[HID];
    for (int i = threadIdx.x; i < HID * HID; i += blockDim.x) Wsm[i] = W[i];
    if (threadIdx.x < HID) bsm[threadIdx.x] = b[threadIdx.x];
    __syncthreads();
    int node = blockIdx.x * 8 + (threadIdx.x >> 5);
    int lane = threadIdx.x & 31;
    if (node >= N_NODES) return;

    const float4* __restrict__ hin = g_h[parity];
    float* __restrict__ hout = (float*)g_h[parity ^ 1];

    int e4   = g_offs[node] >> 2;
    int end4 = g_offs[node + 1] >> 2;
    int grp = lane >> 3, sub = lane & 7;

    float4 accA = make_float4(0.f, 0.f, 0.f, 0.f);
    float4 accB = make_float4(0.f, 0.f, 0.f, 0.f);
    for (; e4 + 2 <= end4; e4 += 2) {
        int4 sA = __ldg(&g_csr4[e4]);
        int4 sB = __ldg(&g_csr4[e4 + 1]);
        int srcA = (grp == 0) ? sA.x : (grp == 1) ? sA.y : (grp == 2) ? sA.z : sA.w;
        int srcB = (grp == 0) ? sB.x : (grp == 1) ? sB.y : (grp == 2) ? sB.z : sB.w;
        float4 vA = hin[(size_t)srcA * 8 + sub];
        float4 vB = hin[(size_t)srcB * 8 + sub];
        accA.x += vA.x; accA.y += vA.y; accA.z += vA.z; accA.w += vA.w;
        accB.x += vB.x; accB.y += vB.y; accB.z += vB.z; accB.w += vB.w;
    }
    if (e4 < end4) {
        int4 sA = __ldg(&g_csr4[e4]);
        int srcA = (grp == 0) ? sA.x : (grp == 1) ? sA.y : (grp == 2) ? sA.z : sA.w;
        float4 vA = hin[(size_t)srcA * 8 + sub];
        accA.x += vA.x; accA.y += vA.y; accA.z += vA.z; accA.w += vA.w;
    }
    accA.x += accB.x; accA.y += accB.y; accA.z += accB.z; accA.w += accB.w;

    // reduce across the 4 lane groups (channels live at fixed sub positions)
#pragma unroll
    for (int d = 8; d <= 16; d <<= 1) {
        accA.x += __shfl_xor_sync(0xffffffffu, accA.x, d);
        accA.y += __shfl_xor_sync(0xffffffffu, accA.y, d);
        accA.z += __shfl_xor_sync(0xffffffffu, accA.z, d);
        accA.w += __shfl_xor_sync(0xffffffffu, accA.w, d);
    }
    // remap: lane wants channel==lane (held at lane lane>>2, component lane&3)
    float a0 = __shfl_sync(0xffffffffu, accA.x, lane >> 2);
    float a1 = __shfl_sync(0xffffffffu, accA.y, lane >> 2);
    float a2 = __shfl_sync(0xffffffffu, accA.z, lane >> 2);
    float a3 = __shfl_sync(0xffffffffu, accA.w, lane >> 2);
    int m = lane & 3;
    float agg = (m == 0) ? a0 : (m == 1) ? a1 : (m == 2) ? a2 : a3;

    float dv = g_dinv[node];
    agg *= dv;

    float y = bsm[lane];
#pragma unroll
    for (int c = 0; c < 32; c++)
        y = fmaf(__shfl_sync(0xffffffffu, agg, c), Wsm[c * HID + lane], y);
    hout[(size_t)node * 32 + lane] = fmaxf(y, 0.f) * dv;   // pre-scale for next layer
}

// ---------------- final launch: out = h @ W32 + b32  (unscale h' by sqrt(deg)) ----------------
__global__ void k_conv_out(int parity, const float* __restrict__ W32,
                           const float* __restrict__ b32, float* __restrict__ out) {
    __shared__ float Wsm[HID * OUT_CH];  // 8 KB
    __shared__ float bsm[OUT_CH];
    for (int i = threadIdx.x; i < HID * OUT_CH; i += blockDim.x) Wsm[i] = W32[i];
    if (threadIdx.x < OUT_CH) bsm[threadIdx.x] = b32[threadIdx.x];
    __syncthreads();
    int node = blockIdx.x * 8 + (threadIdx.x >> 5);
    int lane = threadIdx.x & 31;
    if (node >= N_NODES) return;
    float hv = ((const float*)g_h[parity])[(size_t)node * 32 + lane]
               * sqrtf((float)g_deg[node]);   // undo the dinv pre-scale
    float y0 = bsm[lane], y1 = bsm[lane + 32];
#pragma unroll
    for (int c = 0; c < 32; c++) {
        float a = __shfl_sync(0xffffffffu, hv, c);
        y0 = fmaf(a, Wsm[c * OUT_CH + lane], y0);
        y1 = fmaf(a, Wsm[c * OUT_CH + lane + 32], y1);
    }
    out[(size_t)node * OUT_CH + lane]      = y0;
    out[(size_t)node * OUT_CH + lane + 32] = y1;
}

// ---------------- launch ----------------
extern "C" void kernel_launch(void* const* d_in, const int* in_sizes, int n_in,
                              void* d_out, int out_size) {
    const float* x = nullptr; const float* W0 = nullptr; const float* b0 = nullptr;
    const float* Ws = nullptr; const float* bs = nullptr;
    const float* W32 = nullptr; const float* b32 = nullptr;
    const void* ei = nullptr;
    for (int i = 0; i < n_in; i++) {
        switch (in_sizes[i]) {
            case 12800000: x   = (const float*)d_in[i]; break;
            case 4096:     W0  = (const float*)d_in[i]; break;
            case 32:       b0  = (const float*)d_in[i]; break;
            case 31744:    Ws  = (const float*)d_in[i]; break;
            case 992:      bs  = (const float*)d_in[i]; break;
            case 2048:     W32 = (const float*)d_in[i]; break;
            case 64:       b32 = (const float*)d_in[i]; break;
            case 6400000:  ei  = d_in[i]; break;
            default: break;
        }
    }
    if (!x || !W0 || !b0 || !Ws || !bs || !W32 || !b32 || !ei) return;

    float* out = (float*)d_out;
    const int T = 256;

    // exactly 5 launches before the first sg_layer (so ncu -s 5 -c 1 captures it)
    k_detect_init<<<(N_NODES + T - 1) / T, T>>>((const int*)ei);          // 1
    k_deg_accum<<<(N_EDGES + T - 1) / T, T>>>(ei);                        // 2
    k_scan_dinv<<<1, 1024>>>();                                           // 3
    k_prep<<<(N_PAD_MAX / 4 + T - 1) / T, T>>>();                         // 4
    k_fill_conv0<<<FILL_B + CONV_B, T>>>(ei, x, W0, b0);                  // 5

    int parity = 0;
    for (int l = 0; l < N_SG; l++) {                                      // 6..36
        k_sg_layer<<<CONV_B, T>>>(parity, Ws + (size_t)l * HID * HID, bs + (size_t)l * HID);
        parity ^= 1;
    }

    k_conv_out<<<CONV_B, T>>>(parity, W32, b32, out);                     // 37
}